// round 1
// baseline (speedup 1.0000x reference)
#include <cuda_runtime.h>
#include <stdint.h>

#define NODES 50000
#define DD 64

// ---------------- scratch (no allocations allowed) ----------------
__device__ __align__(16) float g_ha[NODES * DD];    // x @ W1[0:64]  + b1   (dst half)
__device__ __align__(16) float g_hb[NODES * DD];    // x @ W1[64:128]       (src half)
__device__ __align__(16) float g_S[NODES * DD];     // sum over edges of relu(ha[dst]+hb[src])
__device__ __align__(16) float g_aggr[NODES * DD];  // S @ W2 + deg*b2
__device__ __align__(16) float g_hid[NODES * DD];   // relu([x,aggr] @ U1 + ub1)
__device__ __align__(16) float g_deg[NODES];        // in-degree (as float)
__device__ int g_is64;                              // edge_index dtype flag

// ---------------- dtype detection for edge_index ----------------
// If data is int64 (little-endian), the high 32-bit word of each value is 0
// and the low word is a valid node id. If data is int32, "high words" are
// actual random node ids (~0 chance all 16 are zero).
__global__ void detect_kernel(const void* __restrict__ idx) {
    const int* p = (const int*)idx;
    int is64 = 1;
    for (int i = 0; i < 16; i++) {
        int lo = p[2 * i], hi = p[2 * i + 1];
        if (hi != 0 || lo < 0 || lo >= NODES) is64 = 0;
    }
    g_is64 = is64;
}

// ---------------- zero scratch accumulators ----------------
__global__ void zero_kernel() {
    int i = blockIdx.x * blockDim.x + threadIdx.x;
    int stride = gridDim.x * blockDim.x;
    for (int j = i; j < NODES * DD; j += stride) g_S[j] = 0.0f;
    for (int j = i; j < NODES; j += stride) g_deg[j] = 0.0f;
}

// ---------------- generic node-level GEMM ----------------
// C[n,64] = act( A1[n,64] @ W[0:64,:] (+ A2[n,64] @ W[64:128,:]) + bias * rowscale )
// BM=64 rows/block, BN=64 cols, 256 threads, each thread computes 4x4 outputs.
__launch_bounds__(256)
__global__ void gemm_kernel(const float* __restrict__ A1,
                            const float* __restrict__ A2,
                            const float* __restrict__ W,
                            const float* __restrict__ bias,
                            const float* __restrict__ rowscale,
                            float* __restrict__ C,
                            int n, int do_relu) {
    __shared__ float As[DD][DD + 1];  // transposed: As[k][r]  (+1 pad kills store conflicts)
    __shared__ float Ws[DD][DD];      // Ws[k][c]

    const int tid = threadIdx.x;
    const int row0 = blockIdx.x * DD;

    float acc[4][4] = {};

    const int npass = (A2 != nullptr) ? 2 : 1;
    for (int pass = 0; pass < npass; pass++) {
        const float* A = pass ? A2 : A1;
        const float* Wp = W + pass * DD * DD;

        // --- load A tile (transposed into As) and W tile ---
        {
            const int r = tid >> 2;            // 0..63
            const int k0 = (tid & 3) * 16;     // 0,16,32,48
            const int gr = row0 + r;
#pragma unroll
            for (int q = 0; q < 4; q++) {
                float4 f = make_float4(0.f, 0.f, 0.f, 0.f);
                if (gr < n) f = *(const float4*)(A + (size_t)gr * DD + k0 + q * 4);
                As[k0 + q * 4 + 0][r] = f.x;
                As[k0 + q * 4 + 1][r] = f.y;
                As[k0 + q * 4 + 2][r] = f.z;
                As[k0 + q * 4 + 3][r] = f.w;
            }
#pragma unroll
            for (int q = 0; q < 4; q++) {
                *(float4*)&Ws[r][k0 + q * 4] =
                    *(const float4*)(Wp + (size_t)r * DD + k0 + q * 4);
            }
        }
        __syncthreads();

        // --- compute: 4 rows x 4 cols per thread ---
        const int ty = tid >> 4, tx = tid & 15;
        const int r0 = ty * 4, c0 = tx * 4;
#pragma unroll 8
        for (int k = 0; k < DD; k++) {
            const float4 w = *(const float4*)&Ws[k][c0];
            const float a0 = As[k][r0 + 0];
            const float a1 = As[k][r0 + 1];
            const float a2 = As[k][r0 + 2];
            const float a3 = As[k][r0 + 3];
            acc[0][0] = fmaf(a0, w.x, acc[0][0]);
            acc[0][1] = fmaf(a0, w.y, acc[0][1]);
            acc[0][2] = fmaf(a0, w.z, acc[0][2]);
            acc[0][3] = fmaf(a0, w.w, acc[0][3]);
            acc[1][0] = fmaf(a1, w.x, acc[1][0]);
            acc[1][1] = fmaf(a1, w.y, acc[1][1]);
            acc[1][2] = fmaf(a1, w.z, acc[1][2]);
            acc[1][3] = fmaf(a1, w.w, acc[1][3]);
            acc[2][0] = fmaf(a2, w.x, acc[2][0]);
            acc[2][1] = fmaf(a2, w.y, acc[2][1]);
            acc[2][2] = fmaf(a2, w.z, acc[2][2]);
            acc[2][3] = fmaf(a2, w.w, acc[2][3]);
            acc[3][0] = fmaf(a3, w.x, acc[3][0]);
            acc[3][1] = fmaf(a3, w.y, acc[3][1]);
            acc[3][2] = fmaf(a3, w.z, acc[3][2]);
            acc[3][3] = fmaf(a3, w.w, acc[3][3]);
        }
        __syncthreads();
    }

    // --- epilogue ---
    const int ty = tid >> 4, tx = tid & 15;
    const int r0 = ty * 4, c0 = tx * 4;
    float4 bv = make_float4(0.f, 0.f, 0.f, 0.f);
    if (bias) bv = *(const float4*)(bias + c0);
#pragma unroll
    for (int i = 0; i < 4; i++) {
        const int gr = row0 + r0 + i;
        if (gr >= n) break;
        const float s = rowscale ? rowscale[gr] : 1.0f;
        float4 o;
        o.x = acc[i][0] + bv.x * s;
        o.y = acc[i][1] + bv.y * s;
        o.z = acc[i][2] + bv.z * s;
        o.w = acc[i][3] + bv.w * s;
        if (do_relu) {
            o.x = fmaxf(o.x, 0.f);
            o.y = fmaxf(o.y, 0.f);
            o.z = fmaxf(o.z, 0.f);
            o.w = fmaxf(o.w, 0.f);
        }
        *(float4*)(C + (size_t)gr * DD + c0) = o;
    }
}

// ---------------- edge scatter kernel ----------------
// 16 threads per edge; each thread handles one float4 (4 of 64 channels).
// S[dst] += relu(ha[dst] + hb[src]);  deg[dst] += 1
__launch_bounds__(256)
__global__ void edge_kernel(const void* __restrict__ eidx, int E) {
    const int t = blockIdx.x * blockDim.x + threadIdx.x;
    const int e = t >> 4;
    if (e >= E) return;
    const int lane = t & 15;

    int src, dst;
    if (g_is64) {
        const long long* p = (const long long*)eidx;
        src = (int)__ldg(&p[e]);
        dst = (int)__ldg(&p[E + e]);
    } else {
        const int* p = (const int*)eidx;
        src = __ldg(&p[e]);
        dst = __ldg(&p[E + e]);
    }

    const float4 a = __ldg((const float4*)(g_ha + (size_t)dst * DD) + lane);
    const float4 b = __ldg((const float4*)(g_hb + (size_t)src * DD) + lane);
    float4 v;
    v.x = fmaxf(a.x + b.x, 0.f);
    v.y = fmaxf(a.y + b.y, 0.f);
    v.z = fmaxf(a.z + b.z, 0.f);
    v.w = fmaxf(a.w + b.w, 0.f);

    float* p = g_S + (size_t)dst * DD + lane * 4;
    asm volatile("red.global.add.v4.f32 [%0], {%1, %2, %3, %4};"
                 :: "l"(p), "f"(v.x), "f"(v.y), "f"(v.z), "f"(v.w)
                 : "memory");

    if (lane == 0) atomicAdd(&g_deg[dst], 1.0f);
}

// ---------------- launch ----------------
extern "C" void kernel_launch(void* const* d_in, const int* in_sizes, int n_in,
                              void* d_out, int out_size) {
    const float* x   = (const float*)d_in[0];
    const void*  eix = d_in[1];
    const float* W1  = (const float*)d_in[2];
    const float* b1  = (const float*)d_in[3];
    const float* W2  = (const float*)d_in[4];
    const float* b2  = (const float*)d_in[5];
    const float* U1  = (const float*)d_in[6];
    const float* ub1 = (const float*)d_in[7];
    const float* U2  = (const float*)d_in[8];
    const float* ub2 = (const float*)d_in[9];
    float* out = (float*)d_out;

    const int n = in_sizes[0] / DD;   // 50000
    const int E = in_sizes[1] / 2;    // 800000

    // resolve scratch addresses (host-side query; capture-safe, no stream work)
    float *ha, *hb, *S, *aggr, *hid, *deg;
    cudaGetSymbolAddress((void**)&ha,   g_ha);
    cudaGetSymbolAddress((void**)&hb,   g_hb);
    cudaGetSymbolAddress((void**)&S,    g_S);
    cudaGetSymbolAddress((void**)&aggr, g_aggr);
    cudaGetSymbolAddress((void**)&hid,  g_hid);
    cudaGetSymbolAddress((void**)&deg,  g_deg);

    const int nb = (n + DD - 1) / DD;  // 782 row-tiles

    detect_kernel<<<1, 1>>>(eix);
    zero_kernel<<<512, 256>>>();

    // per-node halves of the message MLP's first layer (bias folded into ha)
    gemm_kernel<<<nb, 256>>>(x, nullptr, W1,           b1,      nullptr, ha, n, 0);
    gemm_kernel<<<nb, 256>>>(x, nullptr, W1 + DD * DD, nullptr, nullptr, hb, n, 0);

    // edge phase: S[dst] += relu(ha[dst] + hb[src]); deg[dst]++
    {
        const long long tot = (long long)E * 16;
        const int grid = (int)((tot + 255) / 256);
        edge_kernel<<<grid, 256>>>(eix, E);
    }

    // aggr = S @ W2 + deg*b2   (second message layer pulled through the segment-sum)
    gemm_kernel<<<nb, 256>>>(S, nullptr, W2, b2, deg, aggr, n, 0);

    // hid = relu(x @ U1[0:64] + aggr @ U1[64:128] + ub1)
    gemm_kernel<<<nb, 256>>>(x, aggr, U1, ub1, nullptr, hid, n, 1);

    // out = hid @ U2 + ub2
    gemm_kernel<<<nb, 256>>>(hid, nullptr, U2, ub2, nullptr, out, n, 0);
}